// round 4
// baseline (speedup 1.0000x reference)
#include <cuda_runtime.h>

// Problem constants
#define B_CH   256
#define CH     32
#define B      8          // B_CH / CH
#define H      8
#define E      64
#define L      32         // patch_num = WIN/p
#define P      8          // patch size
#define WIN    256

// Scratch: channel-mean softmax scores
__device__ float g_ps[B * H * L * L];   // 65536 floats
__device__ float g_pn[B * H * P * P];   // 4096 floats

// Packed dual-FMA (sm_103a): d = a*b + d on two f32 lanes at once.
#define FMA2(d, a, b) \
    asm("fma.rn.f32x2 %0, %1, %2, %0;" : "+l"(d) : "l"(a), "l"(b))

__device__ __forceinline__ float unpack_sum(unsigned long long v) {
    float lo = __uint_as_float((unsigned)(v & 0xffffffffu));
    float hi = __uint_as_float((unsigned)(v >> 32));
    return lo + hi;
}

// ---------------------------------------------------------------------------
// Kernel 0: zero the scratch accumulators (graph replays re-use them)
// ---------------------------------------------------------------------------
__global__ __launch_bounds__(256) void zero_scratch_kernel() {
    int idx = blockIdx.x * 256 + threadIdx.x;       // float4 index
    if (idx < (B * H * L * L) / 4) ((float4*)g_ps)[idx] = make_float4(0,0,0,0);
    else {
        int j = idx - (B * H * L * L) / 4;
        if (j < (B * H * P * P) / 4) ((float4*)g_pn)[j] = make_float4(0,0,0,0);
    }
}

// ---------------------------------------------------------------------------
// Kernel 1: fused attention. Blocks [0,2048): patch_size branch, one block
// per (bc, h). Blocks [2048, 2304): patch_num branch, one block per bc.
// 128 threads per block.
// ---------------------------------------------------------------------------
__global__ __launch_bounds__(128) void attn_fused_kernel(
    const float* __restrict__ q_ps, const float* __restrict__ k_ps,
    const float* __restrict__ q_pn, const float* __restrict__ k_pn)
{
    __shared__ float4 sm[2056];     // ps: qs[512] + ks[544] ; pn: qs[1024] + ks[1032]

    if (blockIdx.x < 2048) {
        // ---------------- patch_size branch ----------------
        const int bc = blockIdx.x >> 3;
        const int h  = blockIdx.x & 7;

        float4* qs = sm;            // [row][e4]  (L*16 = 512)
        float4* ks = sm + 512;      // [col][e4] pad 17 (L*17 = 544)

        const float* qb = q_ps + (size_t)bc * (L * H * E) + h * E;
        const float* kb = k_ps + (size_t)bc * (L * H * E) + h * E;

        for (int i = threadIdx.x; i < 2 * L * 16; i += 128) {
            int which = i >> 9;
            int r     = (i >> 4) & (L - 1);
            int e4    = i & 15;
            if (which == 0) qs[r * 16 + e4] = ((const float4*)(qb + r * H * E))[e4];
            else            ks[r * 17 + e4] = ((const float4*)(kb + r * H * E))[e4];
        }
        __syncthreads();

        const int warp = threadIdx.x >> 5;
        const int lane = threadIdx.x & 31;          // = column

        unsigned long long acc0 = 0, acc1 = 0, acc2 = 0, acc3 = 0;
        unsigned long long acc4 = 0, acc5 = 0, acc6 = 0, acc7 = 0;

        const ulonglong2* ks2 = (const ulonglong2*)(ks + lane * 17);
        const ulonglong2* qs2 = (const ulonglong2*)(qs + warp * 8 * 16);

#pragma unroll
        for (int e4 = 0; e4 < 16; ++e4) {
            ulonglong2 kv = ks2[e4];
            ulonglong2 qv;
            qv = qs2[0 * 16 + e4]; FMA2(acc0, qv.x, kv.x); FMA2(acc0, qv.y, kv.y);
            qv = qs2[1 * 16 + e4]; FMA2(acc1, qv.x, kv.x); FMA2(acc1, qv.y, kv.y);
            qv = qs2[2 * 16 + e4]; FMA2(acc2, qv.x, kv.x); FMA2(acc2, qv.y, kv.y);
            qv = qs2[3 * 16 + e4]; FMA2(acc3, qv.x, kv.x); FMA2(acc3, qv.y, kv.y);
            qv = qs2[4 * 16 + e4]; FMA2(acc4, qv.x, kv.x); FMA2(acc4, qv.y, kv.y);
            qv = qs2[5 * 16 + e4]; FMA2(acc5, qv.x, kv.x); FMA2(acc5, qv.y, kv.y);
            qv = qs2[6 * 16 + e4]; FMA2(acc6, qv.x, kv.x); FMA2(acc6, qv.y, kv.y);
            qv = qs2[7 * 16 + e4]; FMA2(acc7, qv.x, kv.x); FMA2(acc7, qv.y, kv.y);
        }

        float accf[8];
        accf[0] = unpack_sum(acc0); accf[1] = unpack_sum(acc1);
        accf[2] = unpack_sum(acc2); accf[3] = unpack_sum(acc3);
        accf[4] = unpack_sum(acc4); accf[5] = unpack_sum(acc5);
        accf[6] = unpack_sum(acc6); accf[7] = unpack_sum(acc7);

        const int bb = bc >> 5;
        float* dst = g_ps + (((bb * H + h) * L) + warp * 8) * L;

#pragma unroll
        for (int r = 0; r < 8; ++r) {
            float s = accf[r] * 0.125f;             // 1/sqrt(E)
            float m = s;
#pragma unroll
            for (int o = 16; o > 0; o >>= 1)
                m = fmaxf(m, __shfl_xor_sync(0xffffffffu, m, o));
            float ev = __expf(s - m);
            float sum = ev;
#pragma unroll
            for (int o = 16; o > 0; o >>= 1)
                sum += __shfl_xor_sync(0xffffffffu, sum, o);
            atomicAdd(dst + r * L + lane, ev * (1.0f / (float)CH) / sum);
        }
    } else {
        // ---------------- patch_num branch ----------------
        const int bc = blockIdx.x - 2048;

        float4* qs = sm;            // [r][h][e4] contiguous (1024)
        float4* ks = sm + 1024;     // [j][h*16+e4] pad 129   (1032)

        const float* qb = q_pn + (size_t)bc * (P * H * E);
        const float* kb = k_pn + (size_t)bc * (P * H * E);

        for (int i = threadIdx.x; i < 1024; i += 128) {
            qs[i] = ((const float4*)qb)[i];
            int j = i >> 7;
            int rest = i & 127;
            ks[j * 129 + rest] = ((const float4*)kb)[i];
        }
        __syncthreads();

        const int t  = threadIdx.x;
        const int r  = (t >> 3) & 7;
        const int j  = t & 7;
        const int hb = (t >> 6) * 4;                // 4 heads per thread
        const int bb = bc >> 5;

#pragma unroll
        for (int hi = 0; hi < 4; ++hi) {
            const int h = hb + hi;
            unsigned long long a2 = 0;
            const ulonglong2* qv2 = (const ulonglong2*)(qs + (r * H + h) * 16);
            const ulonglong2* kv2 = (const ulonglong2*)(ks + j * 129 + h * 16);
#pragma unroll
            for (int e4 = 0; e4 < 16; ++e4) {
                ulonglong2 kv = kv2[e4];
                ulonglong2 qv = qv2[e4];
                FMA2(a2, qv.x, kv.x);
                FMA2(a2, qv.y, kv.y);
            }
            float s = unpack_sum(a2) * 0.125f;
            float m = s;
#pragma unroll
            for (int o = 4; o > 0; o >>= 1)
                m = fmaxf(m, __shfl_xor_sync(0xffffffffu, m, o));
            float ev = __expf(s - m);
            float sum = ev;
#pragma unroll
            for (int o = 4; o > 0; o >>= 1)
                sum += __shfl_xor_sync(0xffffffffu, sum, o);
            atomicAdd(g_pn + (((bb * H + h) * P) + r) * P + j,
                      ev * (1.0f / (float)CH) / sum);
        }
    }
}

// ---------------------------------------------------------------------------
// Kernel 2: expansion. One thread per SOURCE element.
//  threads [0, 65536): ps — 1 coalesced load, 16 STG.128 (8x8 splat)
//  threads [65536, 196608): pn — 2 loads, 8 STG.128 (row-eighth tile)
// Total threads = B*H*L*L + B*H*WIN*P = 65536 + 131072 = 196608 -> 768 blocks.
// Boundary 65536 is block-aligned (256 blocks), so no intra-block divergence.
// ---------------------------------------------------------------------------
__global__ __launch_bounds__(256) void expand_kernel(float* __restrict__ out)
{
    const int idx = blockIdx.x * 256 + threadIdx.x;
    float4* o4 = (float4*)out;

    if (idx < B * H * L * L) {
        // ps: idx = bh*1024 + I*32 + J
        const int J  = idx & 31;
        const int I  = (idx >> 5) & 31;
        const int bh = idx >> 10;
        float v = g_ps[idx];                        // fully coalesced
        float4 vv = make_float4(v, v, v, v);
        float4* base = o4 + (size_t)bh * 16384 + (I * 8) * 64 + J * 2;
#pragma unroll
        for (int rr = 0; rr < 8; ++rr) {
            base[rr * 64]     = vv;
            base[rr * 64 + 1] = vv;
        }
    } else {
        // pn: t = bh*2048 + i*8 + j8   (j8 = eighth of a 256-float row)
        const int t  = idx - B * H * L * L;
        const int j8 = t & 7;
        const int i  = (t >> 3) & 255;
        const int bh = t >> 11;
        const float4* pn4 = (const float4*)g_pn + ((size_t)bh * P + (i & 7)) * 2;
        float4 p0 = pn4[0], p1 = pn4[1];
        float4* base = o4 + (size_t)(B * H * WIN * WIN / 4)
                          + (size_t)bh * 16384 + i * 64 + j8 * 8;
        base[0] = p0; base[1] = p1;
        base[2] = p0; base[3] = p1;
        base[4] = p0; base[5] = p1;
        base[6] = p0; base[7] = p1;
    }
}

// ---------------------------------------------------------------------------
extern "C" void kernel_launch(void* const* d_in, const int* in_sizes, int n_in,
                              void* d_out, int out_size)
{
    const float* q_ps = (const float*)d_in[0];
    const float* k_ps = (const float*)d_in[1];
    const float* q_pn = (const float*)d_in[2];
    const float* k_pn = (const float*)d_in[3];
    float* out = (float*)d_out;

    zero_scratch_kernel<<<68, 256>>>();
    attn_fused_kernel<<<2048 + 256, 128>>>(q_ps, k_ps, q_pn, k_pn);
    // threads = B*H*L*L (ps) + B*H*WIN*P (pn) = 196608 -> 768 blocks
    expand_kernel<<<768, 256>>>(out);
}

// round 5
// speedup vs baseline: 1.0471x; 1.0471x over previous
#include <cuda_runtime.h>

// Problem constants
#define B_CH   256
#define CH     32
#define B      8          // B_CH / CH
#define H      8
#define E      64
#define L      32         // patch_num = WIN/p
#define P      8          // patch size
#define WIN    256

// Scratch: channel-mean softmax scores.
// Zero-initialized at module load; expand_kernel re-zeroes g_ps each replay.
// g_pn is plainly overwritten every replay (no atomics), so it needs no zeroing.
__device__ float g_ps[B * H * L * L];   // 65536 floats
__device__ float g_pn[B * H * P * P];   // 4096 floats

// Packed dual-FMA (sm_103a): d = a*b + d on two f32 lanes at once.
#define FMA2(d, a, b) \
    asm("fma.rn.f32x2 %0, %1, %2, %0;" : "+l"(d) : "l"(a), "l"(b))

__device__ __forceinline__ float unpack_sum(unsigned long long v) {
    float lo = __uint_as_float((unsigned)(v & 0xffffffffu));
    float hi = __uint_as_float((unsigned)(v >> 32));
    return lo + hi;
}

// ---------------------------------------------------------------------------
// Fused attention.
//  Blocks [0, 64):    patch_num branch, one block per (b, h); reduces all 32
//                     channels in-block -> plain store to g_pn (no atomics).
//  Blocks [64, 2112): patch_size branch, one block per (bc, h); atomicAdd
//                     channel-mean into g_ps (zeroed by previous expand).
//  128 threads, smem = 1088 float4 = 17.4 KB (ps occupancy ~13 blocks/SM).
// ---------------------------------------------------------------------------
__global__ __launch_bounds__(128) void attn_fused_kernel(
    const float* __restrict__ q_ps, const float* __restrict__ k_ps,
    const float* __restrict__ q_pn, const float* __restrict__ k_pn)
{
    __shared__ float4 sm[1088];

    if (blockIdx.x >= 64) {
        // ---------------- patch_size branch ----------------
        const int bid = blockIdx.x - 64;
        const int bc = bid >> 3;
        const int h  = bid & 7;

        float4* qs = sm;            // [row][e4]  (L*16 = 512)
        float4* ks = sm + 512;      // [col][e4] pad 17 (L*17 = 544)

        const float* qb = q_ps + (size_t)bc * (L * H * E) + h * E;
        const float* kb = k_ps + (size_t)bc * (L * H * E) + h * E;

        for (int i = threadIdx.x; i < 2 * L * 16; i += 128) {
            int which = i >> 9;
            int r     = (i >> 4) & (L - 1);
            int e4    = i & 15;
            if (which == 0) qs[r * 16 + e4] = ((const float4*)(qb + r * H * E))[e4];
            else            ks[r * 17 + e4] = ((const float4*)(kb + r * H * E))[e4];
        }
        __syncthreads();

        const int warp = threadIdx.x >> 5;
        const int lane = threadIdx.x & 31;          // = column

        unsigned long long acc0 = 0, acc1 = 0, acc2 = 0, acc3 = 0;
        unsigned long long acc4 = 0, acc5 = 0, acc6 = 0, acc7 = 0;

        const ulonglong2* ks2 = (const ulonglong2*)(ks + lane * 17);
        const ulonglong2* qs2 = (const ulonglong2*)(qs + warp * 8 * 16);

#pragma unroll
        for (int e4 = 0; e4 < 16; ++e4) {
            ulonglong2 kv = ks2[e4];
            ulonglong2 qv;
            qv = qs2[0 * 16 + e4]; FMA2(acc0, qv.x, kv.x); FMA2(acc0, qv.y, kv.y);
            qv = qs2[1 * 16 + e4]; FMA2(acc1, qv.x, kv.x); FMA2(acc1, qv.y, kv.y);
            qv = qs2[2 * 16 + e4]; FMA2(acc2, qv.x, kv.x); FMA2(acc2, qv.y, kv.y);
            qv = qs2[3 * 16 + e4]; FMA2(acc3, qv.x, kv.x); FMA2(acc3, qv.y, kv.y);
            qv = qs2[4 * 16 + e4]; FMA2(acc4, qv.x, kv.x); FMA2(acc4, qv.y, kv.y);
            qv = qs2[5 * 16 + e4]; FMA2(acc5, qv.x, kv.x); FMA2(acc5, qv.y, kv.y);
            qv = qs2[6 * 16 + e4]; FMA2(acc6, qv.x, kv.x); FMA2(acc6, qv.y, kv.y);
            qv = qs2[7 * 16 + e4]; FMA2(acc7, qv.x, kv.x); FMA2(acc7, qv.y, kv.y);
        }

        float accf[8];
        accf[0] = unpack_sum(acc0); accf[1] = unpack_sum(acc1);
        accf[2] = unpack_sum(acc2); accf[3] = unpack_sum(acc3);
        accf[4] = unpack_sum(acc4); accf[5] = unpack_sum(acc5);
        accf[6] = unpack_sum(acc6); accf[7] = unpack_sum(acc7);

        const int bb = bc >> 5;
        float* dst = g_ps + (((bb * H + h) * L) + warp * 8) * L;

#pragma unroll
        for (int r = 0; r < 8; ++r) {
            float s = accf[r] * 0.125f;             // 1/sqrt(E)
            float m = s;
#pragma unroll
            for (int o = 16; o > 0; o >>= 1)
                m = fmaxf(m, __shfl_xor_sync(0xffffffffu, m, o));
            float ev = __expf(s - m);
            float sum = ev;
#pragma unroll
            for (int o = 16; o > 0; o >>= 1)
                sum += __shfl_xor_sync(0xffffffffu, sum, o);
            atomicAdd(dst + r * L + lane, ev * (1.0f / (float)CH) / sum);
        }
    } else {
        // ---------------- patch_num branch (all 32 channels in-block) ------
        const int b = blockIdx.x >> 3;
        const int h = blockIdx.x & 7;
        const int tid = threadIdx.x;
        const int ch2 = tid >> 6;                   // 0 or 1
        const int r   = (tid >> 3) & 7;             // query row
        const int j   = tid & 7;                    // key col

        float4* qs = sm;            // [c][r*17 + e4]  (4*136 = 544)
        float4* ks = sm + 544;      // [c][j*17 + e4]  (4*136 = 544)

        float mean_acc = 0.0f;

        for (int chunk = 0; chunk < 8; ++chunk) {
            __syncthreads();    // protect smem reuse from previous iteration
            // load 4 channels: q 4*128 f4 + k 4*128 f4 = 1024 f4 (8/thread)
            for (int i = tid; i < 1024; i += 128) {
                int c     = i >> 8;
                int which = (i >> 7) & 1;
                int rr    = (i >> 4) & 7;
                int e4    = i & 15;
                int bc    = b * CH + chunk * 4 + c;
                const float* src = (which ? k_pn : q_pn)
                                 + (size_t)bc * (P * H * E) + rr * (H * E) + h * E;
                float4 v = ((const float4*)src)[e4];
                if (which) ks[c * 136 + rr * 17 + e4] = v;
                else       qs[c * 136 + rr * 17 + e4] = v;
            }
            __syncthreads();

#pragma unroll
            for (int cc = 0; cc < 2; ++cc) {
                int c = ch2 + cc * 2;
                unsigned long long a2 = 0;
                const ulonglong2* qv2 = (const ulonglong2*)(qs + c * 136 + r * 17);
                const ulonglong2* kv2 = (const ulonglong2*)(ks + c * 136 + j * 17);
#pragma unroll
                for (int e4 = 0; e4 < 16; ++e4) {
                    ulonglong2 qv = qv2[e4];
                    ulonglong2 kv = kv2[e4];
                    FMA2(a2, qv.x, kv.x);
                    FMA2(a2, qv.y, kv.y);
                }
                float s = unpack_sum(a2) * 0.125f;
                float m = s;
#pragma unroll
                for (int o = 4; o > 0; o >>= 1)
                    m = fmaxf(m, __shfl_xor_sync(0xffffffffu, m, o));
                float ev = __expf(s - m);
                float sum = ev;
#pragma unroll
                for (int o = 4; o > 0; o >>= 1)
                    sum += __shfl_xor_sync(0xffffffffu, sum, o);
                mean_acc += ev / sum;
            }
        }

        // reduce the two ch2 halves and store (no atomics)
        __syncthreads();
        float* red = (float*)sm;
        red[tid] = mean_acc;
        __syncthreads();
        if (ch2 == 0) {
            g_pn[((b * H + h) * P + r) * P + j] =
                (red[tid] + red[tid + 64]) * (1.0f / (float)CH);
        }
    }
}

// ---------------------------------------------------------------------------
// Expansion. One thread per SOURCE element.
//  threads [0, 65536): ps — 1 coalesced load, 16 STG.128 (8x8 splat),
//                      then re-zero g_ps[idx] (exclusive reader -> safe).
//  threads [65536, 196608): pn — 2 loads, 8 STG.128 (row-eighth tile)
// 196608 threads -> 768 blocks; boundary is block-aligned.
// ---------------------------------------------------------------------------
__global__ __launch_bounds__(256) void expand_kernel(float* __restrict__ out)
{
    const int idx = blockIdx.x * 256 + threadIdx.x;
    float4* o4 = (float4*)out;

    if (idx < B * H * L * L) {
        // ps: idx = bh*1024 + I*32 + J
        const int J  = idx & 31;
        const int I  = (idx >> 5) & 31;
        const int bh = idx >> 10;
        float v = g_ps[idx];                        // fully coalesced
        g_ps[idx] = 0.0f;                           // self-clean for next replay
        float4 vv = make_float4(v, v, v, v);
        float4* base = o4 + (size_t)bh * 16384 + (I * 8) * 64 + J * 2;
#pragma unroll
        for (int rr = 0; rr < 8; ++rr) {
            base[rr * 64]     = vv;
            base[rr * 64 + 1] = vv;
        }
    } else {
        // pn: t = bh*2048 + i*8 + j8   (j8 = eighth of a 256-float row)
        const int t  = idx - B * H * L * L;
        const int j8 = t & 7;
        const int i  = (t >> 3) & 255;
        const int bh = t >> 11;
        const float4* pn4 = (const float4*)g_pn + ((size_t)bh * P + (i & 7)) * 2;
        float4 p0 = pn4[0], p1 = pn4[1];
        float4* base = o4 + (size_t)(B * H * WIN * WIN / 4)
                          + (size_t)bh * 16384 + i * 64 + j8 * 8;
        base[0] = p0; base[1] = p1;
        base[2] = p0; base[3] = p1;
        base[4] = p0; base[5] = p1;
        base[6] = p0; base[7] = p1;
    }
}

// ---------------------------------------------------------------------------
extern "C" void kernel_launch(void* const* d_in, const int* in_sizes, int n_in,
                              void* d_out, int out_size)
{
    const float* q_ps = (const float*)d_in[0];
    const float* k_ps = (const float*)d_in[1];
    const float* q_pn = (const float*)d_in[2];
    const float* k_pn = (const float*)d_in[3];
    float* out = (float*)d_out;

    attn_fused_kernel<<<64 + 2048, 128>>>(q_ps, k_ps, q_pn, k_pn);
    expand_kernel<<<768, 256>>>(out);
}

// round 6
// speedup vs baseline: 1.2431x; 1.1872x over previous
#include <cuda_runtime.h>

// Problem constants
#define B_CH   256
#define CH     32
#define B      8          // B_CH / CH
#define H      8
#define E      64
#define L      32         // patch_num = WIN/p
#define P      8          // patch size
#define WIN    256

// Scratch: channel-mean softmax scores.
// Zero-initialized at module load; expand_kernel re-zeroes g_ps each replay.
// g_pn is plainly overwritten every replay (no atomics), so it needs no zeroing.
__device__ float g_ps[B * H * L * L];   // 65536 floats
__device__ float g_pn[B * H * P * P];   // 4096 floats

// Packed dual-FMA (sm_103a): d = a*b + d on two f32 lanes at once.
#define FMA2(d, a, b) \
    asm("fma.rn.f32x2 %0, %1, %2, %0;" : "+l"(d) : "l"(a), "l"(b))

__device__ __forceinline__ float unpack_sum(unsigned long long v) {
    float lo = __uint_as_float((unsigned)(v & 0xffffffffu));
    float hi = __uint_as_float((unsigned)(v >> 32));
    return lo + hi;
}

// ---------------------------------------------------------------------------
// Fused attention.
//  Blocks [0, 64):    patch_num branch, one block per (b, h); reduces all 32
//                     channels in-block -> plain store to g_pn (no atomics).
//  Blocks [64, 2112): patch_size branch, one block per (bc, h); atomicAdd
//                     channel-mean into g_ps (zeroed by previous expand).
//  128 threads, smem = 1088 float4 = 17.4 KB (ps occupancy ~13 blocks/SM).
// ---------------------------------------------------------------------------
__global__ __launch_bounds__(128) void attn_fused_kernel(
    const float* __restrict__ q_ps, const float* __restrict__ k_ps,
    const float* __restrict__ q_pn, const float* __restrict__ k_pn)
{
    __shared__ float4 sm[1088];

    if (blockIdx.x >= 64) {
        // ---------------- patch_size branch ----------------
        const int bid = blockIdx.x - 64;
        const int bc = bid >> 3;
        const int h  = bid & 7;

        float4* qs = sm;            // [row][e4]  (L*16 = 512)
        float4* ks = sm + 512;      // [col][e4] pad 17 (L*17 = 544)

        const float* qb = q_ps + (size_t)bc * (L * H * E) + h * E;
        const float* kb = k_ps + (size_t)bc * (L * H * E) + h * E;

        for (int i = threadIdx.x; i < 2 * L * 16; i += 128) {
            int which = i >> 9;
            int r     = (i >> 4) & (L - 1);
            int e4    = i & 15;
            if (which == 0) qs[r * 16 + e4] = ((const float4*)(qb + r * H * E))[e4];
            else            ks[r * 17 + e4] = ((const float4*)(kb + r * H * E))[e4];
        }
        __syncthreads();

        const int warp = threadIdx.x >> 5;
        const int lane = threadIdx.x & 31;          // = column

        unsigned long long acc0 = 0, acc1 = 0, acc2 = 0, acc3 = 0;
        unsigned long long acc4 = 0, acc5 = 0, acc6 = 0, acc7 = 0;

        const ulonglong2* ks2 = (const ulonglong2*)(ks + lane * 17);
        const ulonglong2* qs2 = (const ulonglong2*)(qs + warp * 8 * 16);

#pragma unroll
        for (int e4 = 0; e4 < 16; ++e4) {
            ulonglong2 kv = ks2[e4];
            ulonglong2 qv;
            qv = qs2[0 * 16 + e4]; FMA2(acc0, qv.x, kv.x); FMA2(acc0, qv.y, kv.y);
            qv = qs2[1 * 16 + e4]; FMA2(acc1, qv.x, kv.x); FMA2(acc1, qv.y, kv.y);
            qv = qs2[2 * 16 + e4]; FMA2(acc2, qv.x, kv.x); FMA2(acc2, qv.y, kv.y);
            qv = qs2[3 * 16 + e4]; FMA2(acc3, qv.x, kv.x); FMA2(acc3, qv.y, kv.y);
            qv = qs2[4 * 16 + e4]; FMA2(acc4, qv.x, kv.x); FMA2(acc4, qv.y, kv.y);
            qv = qs2[5 * 16 + e4]; FMA2(acc5, qv.x, kv.x); FMA2(acc5, qv.y, kv.y);
            qv = qs2[6 * 16 + e4]; FMA2(acc6, qv.x, kv.x); FMA2(acc6, qv.y, kv.y);
            qv = qs2[7 * 16 + e4]; FMA2(acc7, qv.x, kv.x); FMA2(acc7, qv.y, kv.y);
        }

        float accf[8];
        accf[0] = unpack_sum(acc0); accf[1] = unpack_sum(acc1);
        accf[2] = unpack_sum(acc2); accf[3] = unpack_sum(acc3);
        accf[4] = unpack_sum(acc4); accf[5] = unpack_sum(acc5);
        accf[6] = unpack_sum(acc6); accf[7] = unpack_sum(acc7);

        const int bb = bc >> 5;
        float* dst = g_ps + (((bb * H + h) * L) + warp * 8) * L;

#pragma unroll
        for (int r = 0; r < 8; ++r) {
            float s = accf[r] * 0.125f;             // 1/sqrt(E)
            float m = s;
#pragma unroll
            for (int o = 16; o > 0; o >>= 1)
                m = fmaxf(m, __shfl_xor_sync(0xffffffffu, m, o));
            float ev = __expf(s - m);
            float sum = ev;
#pragma unroll
            for (int o = 16; o > 0; o >>= 1)
                sum += __shfl_xor_sync(0xffffffffu, sum, o);
            atomicAdd(dst + r * L + lane, ev * (1.0f / (float)CH) / sum);
        }
    } else {
        // ---------------- patch_num branch (all 32 channels in-block) ------
        const int b = blockIdx.x >> 3;
        const int h = blockIdx.x & 7;
        const int tid = threadIdx.x;
        const int ch2 = tid >> 6;                   // 0 or 1
        const int r   = (tid >> 3) & 7;             // query row
        const int j   = tid & 7;                    // key col

        float4* qs = sm;            // [c][r*17 + e4]  (4*136 = 544)
        float4* ks = sm + 544;      // [c][j*17 + e4]  (4*136 = 544)

        float mean_acc = 0.0f;

        for (int chunk = 0; chunk < 8; ++chunk) {
            __syncthreads();    // protect smem reuse from previous iteration
            // load 4 channels: q 4*128 f4 + k 4*128 f4 = 1024 f4 (8/thread)
            for (int i = tid; i < 1024; i += 128) {
                int c     = i >> 8;
                int which = (i >> 7) & 1;
                int rr    = (i >> 4) & 7;
                int e4    = i & 15;
                int bc    = b * CH + chunk * 4 + c;
                const float* src = (which ? k_pn : q_pn)
                                 + (size_t)bc * (P * H * E) + rr * (H * E) + h * E;
                float4 v = ((const float4*)src)[e4];
                if (which) ks[c * 136 + rr * 17 + e4] = v;
                else       qs[c * 136 + rr * 17 + e4] = v;
            }
            __syncthreads();

#pragma unroll
            for (int cc = 0; cc < 2; ++cc) {
                int c = ch2 + cc * 2;
                unsigned long long a2 = 0;
                const ulonglong2* qv2 = (const ulonglong2*)(qs + c * 136 + r * 17);
                const ulonglong2* kv2 = (const ulonglong2*)(ks + c * 136 + j * 17);
#pragma unroll
                for (int e4 = 0; e4 < 16; ++e4) {
                    ulonglong2 qv = qv2[e4];
                    ulonglong2 kv = kv2[e4];
                    FMA2(a2, qv.x, kv.x);
                    FMA2(a2, qv.y, kv.y);
                }
                float s = unpack_sum(a2) * 0.125f;
                float m = s;
#pragma unroll
                for (int o = 4; o > 0; o >>= 1)
                    m = fmaxf(m, __shfl_xor_sync(0xffffffffu, m, o));
                float ev = __expf(s - m);
                float sum = ev;
#pragma unroll
                for (int o = 4; o > 0; o >>= 1)
                    sum += __shfl_xor_sync(0xffffffffu, sum, o);
                mean_acc += ev / sum;
            }
        }

        // reduce the two ch2 halves and store (no atomics)
        __syncthreads();
        float* red = (float*)sm;
        red[tid] = mean_acc;
        __syncthreads();
        if (ch2 == 0) {
            g_pn[((b * H + h) * P + r) * P + j] =
                (red[tid] + red[tid + 64]) * (1.0f / (float)CH);
        }
    }
}

// ---------------------------------------------------------------------------
// Expansion v3: every STG.128 is warp-contiguous (32 lanes -> 512B, 4 fully
// covered 128B lines). Each block owns a contiguous 4KB output tile (1024
// float4 = 16 output rows); the tiny source row(s) are staged in smem and
// read via broadcast LDS.
//  Blocks [0, 1024):    ps. block -> (bh = b>>4, Ipair = b&15): source rows
//                       {2*Ipair, 2*Ipair+1} (64 floats), output rows
//                       [16*Ipair, 16*Ipair+16). Also re-zeroes its 64
//                       g_ps floats (exclusive reader) for the next replay.
//  Blocks [1024, 2048): pn. block -> (bh, seg): output rows [16*seg,
//                       16*seg+16), pattern = pn[bh] tile (16 float4).
// 4 STG.128 per thread, independent addresses.
// ---------------------------------------------------------------------------
#define PN_BASE (B * H * WIN * WIN / 4)     // float4 offset of second output

__global__ __launch_bounds__(256) void expand_kernel(float* __restrict__ out)
{
    __shared__ float s_src[64];
    float4* o4 = (float4*)out;
    const int t = threadIdx.x;

    if (blockIdx.x < 1024) {
        // ---------------- ps: 8x8 element repeat ----------------
        const int bh = blockIdx.x >> 4;
        const int Ip = blockIdx.x & 15;

        if (t < 64) {
            int gidx = bh * 1024 + Ip * 64 + t;     // [bh][2 rows][32 J]
            float v = g_ps[gidx];
            g_ps[gidx] = 0.0f;                      // self-clean for next replay
            s_src[t] = v;
        }
        __syncthreads();

        float4* base = o4 + (size_t)bh * 16384 + Ip * 16 * 64;
#pragma unroll
        for (int k = 0; k < 4; ++k) {
            int v = k * 256 + t;                    // 0..1023 within tile
            int row = v >> 6;                       // 0..15 (output row)
            int c4  = v & 63;                       // float4 col
            float x = s_src[(row >> 3) * 32 + (c4 >> 1)];
            base[v] = make_float4(x, x, x, x);
        }
    } else {
        // ---------------- pn: 32x32 tile ----------------
        const int b2  = blockIdx.x - 1024;
        const int bh  = b2 >> 4;
        const int seg = b2 & 15;

        float4* s4 = (float4*)s_src;                // 16 float4 = pn[bh] tile
        if (t < 16) s4[t] = ((const float4*)g_pn)[bh * 16 + t];
        __syncthreads();

        float4* base = o4 + (size_t)PN_BASE + (size_t)bh * 16384 + seg * 16 * 64;
#pragma unroll
        for (int k = 0; k < 4; ++k) {
            int v = k * 256 + t;
            int row = v >> 6;                       // 0..15
            int c4  = v & 63;
            int i   = seg * 16 + row;               // global output row
            base[v] = s4[(i & 7) * 2 + (c4 & 1)];
        }
    }
}

// ---------------------------------------------------------------------------
extern "C" void kernel_launch(void* const* d_in, const int* in_sizes, int n_in,
                              void* d_out, int out_size)
{
    const float* q_ps = (const float*)d_in[0];
    const float* k_ps = (const float*)d_in[1];
    const float* q_pn = (const float*)d_in[2];
    const float* k_pn = (const float*)d_in[3];
    float* out = (float*)d_out;

    attn_fused_kernel<<<64 + 2048, 128>>>(q_ps, k_ps, q_pn, k_pn);
    expand_kernel<<<2048, 256>>>(out);
}